// round 12
// baseline (speedup 1.0000x reference)
#include <cuda_runtime.h>
#include <cuda_fp16.h>
#include <cstdint>

// ---------------- problem constants (fixed by the dataset) ----------------
#define NB    240
#define NS    64
#define NHID  768
#define NH    12
#define HD    64
#define L0    384
#define L1    128
#define LTOT  576
#define NCHUNK 9

// device-global scratch (allocation-free); all fp16, NATURAL layouts
__device__ __half g_hidh[(size_t)NB * NS * NHID];       // hidden
__device__ __half g_wh  [(size_t)3 * NHID * NHID];      // Wq|Wk|Wv
__device__ __half g_qh  [(size_t)NB * NH * NS * HD];    // q [bh][s][d]
__device__ __half g_kh  [(size_t)NB * NH * NS * HD];    // k [bh][s][d]
__device__ __half g_vh  [(size_t)NB * NH * NS * HD];    // v [bh][s][d]
__device__ __half g_c0kh[(size_t)8 * NH * L0 * HD];     // c0 key [g][j][d]
__device__ __half g_c0vh[(size_t)8 * NH * L0 * HD];     // c0 val [g][j][d]
__device__ __half g_c1kh[(size_t)NB * NH * L1 * HD];    // c1 key
__device__ __half g_c1vh[(size_t)NB * NH * L1 * HD];    // c1 val

// ---------------- helpers ----------------
__device__ __forceinline__ uint32_t h2u(__half2 h) { return *(uint32_t*)&h; }

__device__ __forceinline__ uint32_t smem_u32(const void* p) {
    uint32_t a;
    asm("{ .reg .u64 t; cvta.to.shared.u64 t, %1; cvt.u32.u64 %0, t; }"
        : "=r"(a) : "l"(p));
    return a;
}

#define MMA_F16(c, a, b0, b1)                                               \
    asm volatile(                                                           \
        "mma.sync.aligned.m16n8k16.row.col.f32.f16.f16.f32 "                \
        "{%0,%1,%2,%3}, {%4,%5,%6,%7}, {%8,%9}, {%0,%1,%2,%3};\n"           \
        : "+f"((c)[0]), "+f"((c)[1]), "+f"((c)[2]), "+f"((c)[3])            \
        : "r"((a)[0]), "r"((a)[1]), "r"((a)[2]), "r"((a)[3]),               \
          "r"(b0), "r"(b1))

__device__ __forceinline__ void ldm_x4(uint32_t& r0, uint32_t& r1,
                                       uint32_t& r2, uint32_t& r3,
                                       uint32_t addr) {
    asm volatile("ldmatrix.sync.aligned.m8n8.x4.shared.b16 {%0,%1,%2,%3}, [%4];"
                 : "=r"(r0), "=r"(r1), "=r"(r2), "=r"(r3) : "r"(addr));
}
__device__ __forceinline__ void ldm_x4_t(uint32_t& r0, uint32_t& r1,
                                         uint32_t& r2, uint32_t& r3,
                                         uint32_t addr) {
    asm volatile("ldmatrix.sync.aligned.m8n8.x4.trans.shared.b16 {%0,%1,%2,%3}, [%4];"
                 : "=r"(r0), "=r"(r1), "=r"(r2), "=r"(r3) : "r"(addr));
}

__device__ __forceinline__ void cp16h(__half* dst, const __half* src) {
    uint32_t d = (uint32_t)__cvta_generic_to_shared(dst);
    asm volatile("cp.async.cg.shared.global [%0], [%1], 16;\n" :: "r"(d), "l"(src));
}
__device__ __forceinline__ void cp16f(float* dst, const float* src) {
    uint32_t d = (uint32_t)__cvta_generic_to_shared(dst);
    asm volatile("cp.async.cg.shared.global [%0], [%1], 16;\n" :: "r"(d), "l"(src));
}
__device__ __forceinline__ void cp_commit() {
    asm volatile("cp.async.commit_group;\n");
}
template <int N> __device__ __forceinline__ void cp_wait() {
    asm volatile("cp.async.wait_group %0;\n" :: "n"(N));
}

// =====================================================================
// Fused float->fp16 conversion over ALL 8 segments (one launch).
// Segment sizes in float4 units.
// =====================================================================
#define SG_HID 2949120
#define SG_W   147456
#define SG_C0  589824
#define SG_C1  5898240
#define SB0 SG_HID
#define SB1 (SB0 + SG_W)
#define SB2 (SB1 + SG_W)
#define SB3 (SB2 + SG_W)
#define SB4 (SB3 + SG_C0)
#define SB5 (SB4 + SG_C0)
#define SB6 (SB5 + SG_C1)
#define SB7 (SB6 + SG_C1)

__global__ __launch_bounds__(256) void cvt_all_kernel(
    const float4* __restrict__ hid, const float4* __restrict__ wq,
    const float4* __restrict__ wk,  const float4* __restrict__ wv,
    const float4* __restrict__ c0k, const float4* __restrict__ c0v,
    const float4* __restrict__ c1k, const float4* __restrict__ c1v,
    uint2* __restrict__ d_hid, uint2* __restrict__ d_w,
    uint2* __restrict__ d_c0k, uint2* __restrict__ d_c0v,
    uint2* __restrict__ d_c1k, uint2* __restrict__ d_c1v)
{
    const int stride = gridDim.x * blockDim.x;
    for (int i = blockIdx.x * blockDim.x + threadIdx.x; i < SB7; i += stride) {
        const float4* s;
        uint2* d;
        if (i < SB0)      { s = hid + i;          d = d_hid + i; }
        else if (i < SB1) { s = wq + (i - SB0);   d = d_w + (i - SB0); }
        else if (i < SB2) { s = wk + (i - SB1);   d = d_w + SG_W + (i - SB1); }
        else if (i < SB3) { s = wv + (i - SB2);   d = d_w + 2 * SG_W + (i - SB2); }
        else if (i < SB4) { s = c0k + (i - SB3);  d = d_c0k + (i - SB3); }
        else if (i < SB5) { s = c0v + (i - SB4);  d = d_c0v + (i - SB4); }
        else if (i < SB6) { s = c1k + (i - SB5);  d = d_c1k + (i - SB5); }
        else              { s = c1v + (i - SB6);  d = d_c1v + (i - SB6); }
        float4 v = *s;
        __half2 lo = __floats2half2_rn(v.x, v.y);
        __half2 hi = __floats2half2_rn(v.z, v.w);
        uint2 o;
        o.x = h2u(lo);
        o.y = h2u(hi);
        *d = o;
    }
}

// =====================================================================
// QKV projection, fp16 mma + ldmatrix, 3-stage cp.async pipeline.
// Block 128x128, BK=32, 8 warps (4x2), warp tile 32x64; 20 KB stages.
// =====================================================================
#define GLDW  20
#define A_W   (128 * GLDW)
#define B_W   (128 * GLDW)
#define STAGEW (A_W + B_W)
#define ROWB  80

__global__ __launch_bounds__(256, 2) void qkv_gemm_f16(
    const float* __restrict__ bq, const float* __restrict__ bk_,
    const float* __restrict__ bv,
    float* __restrict__ out_k, float* __restrict__ out_v)
{
    extern __shared__ uint32_t smw[];
    const uint32_t smem_b = smem_u32(smw);

    const int m0  = blockIdx.x * 128;
    const int n0g = blockIdx.y * 128;
    const int mat = n0g / NHID;
    const int n0  = n0g - mat * NHID;

    const __half* Ag = g_hidh;
    const __half* Bg = g_wh + (size_t)mat * NHID * NHID;
    const float*  bi = (mat == 0) ? bq : (mat == 1) ? bk_ : bv;

    const int tid  = threadIdx.x;
    const int lane = tid & 31;
    const int w    = tid >> 5;
    const int wm   = w & 3;           // 4 m bands of 32
    const int wn   = w >> 2;          // 2 n halves of 64
    const int lq   = lane & 3;
    const int lr   = lane >> 2;

    // ldmatrix per-lane addressing
    const int lg = lane >> 3, lrs = lane & 7;
    const int a_radd = (lg & 1) * 8 + lrs;
    const int a_kadd = (lg >> 1) * 8;
    const int b_radd = (lg >> 1) * 8 + lrs;
    const int b_kadd = (lg & 1) * 8;

    // cp.async staging: A/B each 128 rows x 32 halves = 512 x 16B units
    const int srow = tid >> 1;               // 0..127
    const int sun  = (tid & 1) * 16;         // half offset (2 units of 8)

    auto load_stage = [&](int s, int k0) {
        __half* A = (__half*)smw + s * STAGEW * 2;
        __half* B = A + A_W * 2;
        const __half* ag = Ag + (size_t)(m0 + srow) * NHID + k0 + sun;
        const __half* bg = Bg + (size_t)(n0 + srow) * NHID + k0 + sun;
        cp16h(A + srow * 40 + sun,     ag);
        cp16h(A + srow * 40 + sun + 8, ag + 8);
        cp16h(B + srow * 40 + sun,     bg);
        cp16h(B + srow * 40 + sun + 8, bg + 8);
    };

    float acc[2][8][4];
#pragma unroll
    for (int mt = 0; mt < 2; mt++)
#pragma unroll
        for (int nt = 0; nt < 8; nt++)
#pragma unroll
            for (int i = 0; i < 4; i++) acc[mt][nt][i] = 0.f;

    auto compute = [&](int s) {
        const uint32_t Ab = smem_b + s * STAGEW * 4;
        const uint32_t Bb = Ab + A_W * 4;
#pragma unroll
        for (int ks = 0; ks < 2; ks++) {
            uint32_t af[2][4];
#pragma unroll
            for (int mt = 0; mt < 2; mt++) {
                const uint32_t addr = Ab
                    + (uint32_t)((wm * 32 + mt * 16 + a_radd) * ROWB
                                 + (ks * 16 + a_kadd) * 2);
                ldm_x4(af[mt][0], af[mt][1], af[mt][2], af[mt][3], addr);
            }
            uint32_t bf[8][2];
#pragma unroll
            for (int np = 0; np < 4; np++) {
                const uint32_t addr = Bb
                    + (uint32_t)((wn * 64 + np * 16 + b_radd) * ROWB
                                 + (ks * 16 + b_kadd) * 2);
                ldm_x4(bf[2 * np][0], bf[2 * np][1],
                       bf[2 * np + 1][0], bf[2 * np + 1][1], addr);
            }
#pragma unroll
            for (int mt = 0; mt < 2; mt++)
#pragma unroll
                for (int nt = 0; nt < 8; nt++)
                    MMA_F16(acc[mt][nt], af[mt], bf[nt][0], bf[nt][1]);
        }
    };

    load_stage(0, 0);  cp_commit();
    load_stage(1, 32); cp_commit();

    for (int it = 0; it < 24; it++) {
        if (it < 23) cp_wait<1>(); else cp_wait<0>();
        __syncthreads();
        if (it + 2 < 24) {
            load_stage((it + 2) % 3, (it + 2) * 32);
            cp_commit();
        }
        compute(it % 3);
    }

    // epilogue: bias + scatter; fp16 copies in natural layout
#pragma unroll
    for (int nt = 0; nt < 8; nt++) {
        const int ncol = n0 + wn * 64 + nt * 8 + 2 * lq;
        const float b0 = bi[ncol];
        const float b1 = bi[ncol + 1];
        const int h = ncol >> 6;
        const int d = ncol & 63;
#pragma unroll
        for (int mt = 0; mt < 2; mt++) {
            const int r = wm * 32 + mt * 16 + lr;
#pragma unroll
            for (int half = 0; half < 2; half++) {
                const int m = m0 + r + 8 * half;
                const int b = m >> 6;
                const int s = m & 63;
                const size_t bh = (size_t)b * NH + h;
                float2 v;
                v.x = acc[mt][nt][2 * half + 0] + b0;
                v.y = acc[mt][nt][2 * half + 1] + b1;
                const size_t idx = (bh * 64 + s) * 64 + d;
                if (mat == 0) {
                    *(__half2*)&g_qh[idx] = __floats2half2_rn(v.x, v.y);
                } else if (mat == 1) {
                    *(float2*)&out_k[idx] = v;
                    *(__half2*)&g_kh[idx] = __floats2half2_rn(v.x, v.y);
                } else {
                    *(float2*)&out_v[idx] = v;
                    *(__half2*)&g_vh[idx] = __floats2half2_rn(v.x, v.y);
                }
            }
        }
    }
}

// =====================================================================
// Flash cache attention, fp16 mma + ldmatrix. V consumed from NATURAL
// [j][d] layout via ldmatrix.trans (B fragments of V^T).
// =====================================================================
#define KVH_LD 72
#define KVH_TILE (64 * KVH_LD)
#define KROWB 144

__global__ __launch_bounds__(128, 4) void attn_flash_f16(
    const float* __restrict__ mask,
    float* __restrict__ outctx)
{
    extern __shared__ __half smh[];
    __half* kbuf   = smh;                       // [2][64][72]
    __half* vbuf   = kbuf + 2 * KVH_TILE;       // [2][64][72]
    float*  mask_s = (float*)(vbuf + 2 * KVH_TILE);   // [576]
    const uint32_t kb_b = smem_u32(kbuf);
    const uint32_t vb_b = smem_u32(vbuf);

    const int bh   = blockIdx.x;
    const int b    = bh / NH;
    const int h    = bh - b * NH;
    const int tid  = threadIdx.x;
    const int lane = tid & 31;
    const int w    = tid >> 5;
    const int lq   = lane & 3;
    const int lr   = lane >> 2;

    const int lg = lane >> 3, lrs = lane & 7;
    const int b_radd = (lg >> 1) * 8 + lrs;     // K (non-trans B)
    const int b_kadd = (lg & 1) * 8;
    const int v_radd = (lg & 1) * 8 + lrs;      // V (.trans): rows = k(j)-dim
    const int v_cadd = (lg >> 1) * 8;           //              cols = n(d)-dim

    const __half* c0kb = g_c0kh + ((size_t)(b & 7) * NH + h) * L0 * HD;
    const __half* c0vb = g_c0vh + ((size_t)(b & 7) * NH + h) * L0 * HD;
    const __half* c1kb = g_c1kh + (size_t)bh * L1 * HD;
    const __half* c1vb = g_c1vh + (size_t)bh * L1 * HD;
    const __half* ksb  = g_kh + (size_t)bh * NS * HD;
    const __half* vsb  = g_vh + (size_t)bh * NS * HD;

    auto ksrc_of = [&](int c) -> const __half* {
        return (c < 6) ? (c0kb + c * 64 * HD)
             : (c < 8) ? (c1kb + (c - 6) * 64 * HD) : ksb;
    };
    auto vsrc_of = [&](int c) -> const __half* {
        return (c < 6) ? (c0vb + c * 64 * HD)
             : (c < 8) ? (c1vb + (c - 6) * 64 * HD) : vsb;
    };

    auto load_tile = [&](__half* buf, const __half* src) {
        const int r  = tid >> 1;
        const int c0 = (tid & 1) * 32;
        __half* d = buf + r * KVH_LD + c0;
        const __half* s = src + (size_t)r * HD + c0;
#pragma unroll
        for (int i = 0; i < 4; i++) cp16h(d + 8 * i, s + 8 * i);
    };

    // prologue: Q -> kbuf[1]; chunk0 -> buf0; mask
    load_tile(kbuf + KVH_TILE, g_qh + (size_t)bh * NS * HD);
    cp_commit();
    load_tile(kbuf, ksrc_of(0));
    load_tile(vbuf, vsrc_of(0));
    cp_commit();
    for (int i = tid * 4; i < LTOT; i += 128 * 4)
        cp16f(mask_s + i, mask + (size_t)b * LTOT + i);
    cp_commit();

    cp_wait<2>();
    __syncthreads();

    // Q fragments via ldmatrix (A-operand shape)
    uint32_t qa[4][4];
    {
        const int a_radd = (lg & 1) * 8 + lrs;
        const int a_kadd = (lg >> 1) * 8;
        const uint32_t Qb = kb_b + KVH_TILE * 2;
#pragma unroll
        for (int ks = 0; ks < 4; ks++) {
            const uint32_t addr = Qb
                + (uint32_t)((w * 16 + a_radd) * KROWB + (ks * 16 + a_kadd) * 2);
            ldm_x4(qa[ks][0], qa[ks][1], qa[ks][2], qa[ks][3], addr);
        }
    }
    __syncthreads();

    float m0 = -1e30f, m1 = -1e30f;
    float l0 = 0.f,    l1 = 0.f;
    float o[8][4];
#pragma unroll
    for (int dt = 0; dt < 8; dt++)
#pragma unroll
        for (int i = 0; i < 4; i++) o[dt][i] = 0.f;

    for (int c = 0; c < NCHUNK; c++) {
        if (c < NCHUNK - 1) {
            load_tile(kbuf + ((c + 1) & 1) * KVH_TILE, ksrc_of(c + 1));
            load_tile(vbuf + ((c + 1) & 1) * KVH_TILE, vsrc_of(c + 1));
            cp_commit();
            cp_wait<1>();
        } else {
            cp_wait<0>();
        }
        __syncthreads();

        const uint32_t Kb = kb_b + (c & 1) * KVH_TILE * 2;
        const uint32_t Vb = vb_b + (c & 1) * KVH_TILE * 2;

        // ---- S = Q K^T ----
        float cS[8][4];
#pragma unroll
        for (int nt = 0; nt < 8; nt++)
#pragma unroll
            for (int i = 0; i < 4; i++) cS[nt][i] = 0.f;

#pragma unroll
        for (int ks = 0; ks < 4; ks++) {
#pragma unroll
            for (int np = 0; np < 4; np++) {
                uint32_t b00, b01, b10, b11;
                const uint32_t addr = Kb
                    + (uint32_t)((np * 16 + b_radd) * KROWB + (ks * 16 + b_kadd) * 2);
                ldm_x4(b00, b01, b10, b11, addr);
                MMA_F16(cS[2 * np],     qa[ks], b00, b01);
                MMA_F16(cS[2 * np + 1], qa[ks], b10, b11);
            }
        }

        // ---- mask + scale + chunk row max ----
        float cm0 = -1e30f, cm1 = -1e30f;
#pragma unroll
        for (int nt = 0; nt < 8; nt++) {
            const int col = c * 64 + nt * 8 + 2 * lq;
            const float mv0 = mask_s[col];
            const float mv1 = mask_s[col + 1];
            cS[nt][0] = cS[nt][0] * 0.125f + mv0;
            cS[nt][1] = cS[nt][1] * 0.125f + mv1;
            cS[nt][2] = cS[nt][2] * 0.125f + mv0;
            cS[nt][3] = cS[nt][3] * 0.125f + mv1;
            cm0 = fmaxf(cm0, fmaxf(cS[nt][0], cS[nt][1]));
            cm1 = fmaxf(cm1, fmaxf(cS[nt][2], cS[nt][3]));
        }
#pragma unroll
        for (int off = 1; off <= 2; off <<= 1) {
            cm0 = fmaxf(cm0, __shfl_xor_sync(0xFFFFFFFFu, cm0, off));
            cm1 = fmaxf(cm1, __shfl_xor_sync(0xFFFFFFFFu, cm1, off));
        }

        const float mn0 = fmaxf(m0, cm0);
        const float mn1 = fmaxf(m1, cm1);
        const float a0  = __expf(m0 - mn0);
        const float a1  = __expf(m1 - mn1);
        m0 = mn0; m1 = mn1;

        float s0 = 0.f, s1 = 0.f;
#pragma unroll
        for (int nt = 0; nt < 8; nt++) {
            cS[nt][0] = __expf(cS[nt][0] - mn0);
            cS[nt][1] = __expf(cS[nt][1] - mn0);
            cS[nt][2] = __expf(cS[nt][2] - mn1);
            cS[nt][3] = __expf(cS[nt][3] - mn1);
            s0 += cS[nt][0] + cS[nt][1];
            s1 += cS[nt][2] + cS[nt][3];
        }
#pragma unroll
        for (int off = 1; off <= 2; off <<= 1) {
            s0 += __shfl_xor_sync(0xFFFFFFFFu, s0, off);
            s1 += __shfl_xor_sync(0xFFFFFFFFu, s1, off);
        }
        l0 = l0 * a0 + s0;
        l1 = l1 * a1 + s1;

#pragma unroll
        for (int dt = 0; dt < 8; dt++) {
            o[dt][0] *= a0; o[dt][1] *= a0;
            o[dt][2] *= a1; o[dt][3] *= a1;
        }

        // ---- PV: in-thread P pack, V via ldmatrix.trans ----
#pragma unroll
        for (int kt = 0; kt < 4; kt++) {
            uint32_t pa[4];
            pa[0] = h2u(__floats2half2_rn(cS[2 * kt][0],     cS[2 * kt][1]));
            pa[1] = h2u(__floats2half2_rn(cS[2 * kt][2],     cS[2 * kt][3]));
            pa[2] = h2u(__floats2half2_rn(cS[2 * kt + 1][0], cS[2 * kt + 1][1]));
            pa[3] = h2u(__floats2half2_rn(cS[2 * kt + 1][2], cS[2 * kt + 1][3]));
#pragma unroll
            for (int np = 0; np < 4; np++) {
                uint32_t b00, b01, b10, b11;
                const uint32_t addr = Vb
                    + (uint32_t)((kt * 16 + v_radd) * KROWB
                                 + (np * 16 + v_cadd) * 2);
                ldm_x4_t(b00, b01, b10, b11, addr);
                MMA_F16(o[2 * np],     pa, b00, b01);
                MMA_F16(o[2 * np + 1], pa, b10, b11);
            }
        }
        __syncthreads();
    }

    // epilogue: normalize + write out[b, s, h*64 + d]
    {
        const float r0 = 1.f / l0;
        const float r1 = 1.f / l1;
        const int r = w * 16 + lr;
        float* ob0 = outctx + ((size_t)b * NS + r) * NHID + h * HD;
        float* ob1 = outctx + ((size_t)b * NS + r + 8) * NHID + h * HD;
#pragma unroll
        for (int dt = 0; dt < 8; dt++) {
            const int dcol = dt * 8 + 2 * lq;
            float2 v0, v1;
            v0.x = o[dt][0] * r0; v0.y = o[dt][1] * r0;
            v1.x = o[dt][2] * r1; v1.y = o[dt][3] * r1;
            *(float2*)&ob0[dcol] = v0;
            *(float2*)&ob1[dcol] = v1;
        }
    }
}

// =====================================================================
// Host launcher
// =====================================================================
extern "C" void kernel_launch(void* const* d_in, const int* in_sizes, int n_in,
                              void* d_out, int out_size)
{
    const float* hidden = (const float*)d_in[0];
    const float* mask   = (const float*)d_in[1];
    const float* Wq     = (const float*)d_in[2];
    const float* bq     = (const float*)d_in[3];
    const float* Wk     = (const float*)d_in[4];
    const float* bk     = (const float*)d_in[5];
    const float* Wv     = (const float*)d_in[6];
    const float* bv     = (const float*)d_in[7];
    const float* c0k    = (const float*)d_in[8];
    const float* c0v    = (const float*)d_in[9];
    const float* c1k    = (const float*)d_in[10];
    const float* c1v    = (const float*)d_in[11];

    float* out   = (float*)d_out;
    const size_t sect = (size_t)NB * NS * NHID;
    float* out_k = out + sect;
    float* out_v = out + 2 * sect;

    __half *hidh_d, *wh_d, *c0kh_d, *c0vh_d, *c1kh_d, *c1vh_d;
    cudaGetSymbolAddress((void**)&hidh_d, g_hidh);
    cudaGetSymbolAddress((void**)&wh_d,   g_wh);
    cudaGetSymbolAddress((void**)&c0kh_d, g_c0kh);
    cudaGetSymbolAddress((void**)&c0vh_d, g_c0vh);
    cudaGetSymbolAddress((void**)&c1kh_d, g_c1kh);
    cudaGetSymbolAddress((void**)&c1vh_d, g_c1vh);

    const int gemm_smem = 3 * STAGEW * 4;                 // 61440
    const int attn_smem = 4 * KVH_TILE * 2 + LTOT * 4;    // 39168

    cudaFuncSetAttribute(qkv_gemm_f16,
                         cudaFuncAttributeMaxDynamicSharedMemorySize, gemm_smem);
    cudaFuncSetAttribute(attn_flash_f16,
                         cudaFuncAttributeMaxDynamicSharedMemorySize, attn_smem);

    // preprocessing: ONE fused convert launch (all 8 tensors)
    cvt_all_kernel<<<4096, 256>>>(
        (const float4*)hidden, (const float4*)Wq, (const float4*)Wk,
        (const float4*)Wv, (const float4*)c0k, (const float4*)c0v,
        (const float4*)c1k, (const float4*)c1v,
        (uint2*)hidh_d, (uint2*)wh_d, (uint2*)c0kh_d, (uint2*)c0vh_d,
        (uint2*)c1kh_d, (uint2*)c1vh_d);

    dim3 ggrid(NB * NS / 128, 3 * NHID / 128);       // (120, 18)
    qkv_gemm_f16<<<ggrid, 256, gemm_smem>>>(bq, bk, bv, out_k, out_v);

    attn_flash_f16<<<NB * NH, 128, attn_smem>>>(mask, out);
}

// round 13
// speedup vs baseline: 1.1102x; 1.1102x over previous
#include <cuda_runtime.h>
#include <cuda_fp16.h>
#include <cstdint>

// ---------------- problem constants (fixed by the dataset) ----------------
#define NB    240
#define NS    64
#define NHID  768
#define NH    12
#define HD    64
#define L0    384
#define L1    128
#define LTOT  576
#define NCHUNK 9

// device-global scratch (allocation-free); all fp16, NATURAL layouts
__device__ __half g_hidh[(size_t)NB * NS * NHID];       // hidden
__device__ __half g_wh  [(size_t)3 * NHID * NHID];      // Wq|Wk|Wv
__device__ __half g_qh  [(size_t)NB * NH * NS * HD];    // q [bh][s][d]
__device__ __half g_kh  [(size_t)NB * NH * NS * HD];    // k [bh][s][d]
__device__ __half g_vh  [(size_t)NB * NH * NS * HD];    // v [bh][s][d]
__device__ __half g_c0kh[(size_t)8 * NH * L0 * HD];     // c0 key [g][j][d]
__device__ __half g_c0vh[(size_t)8 * NH * L0 * HD];     // c0 val [g][j][d]
__device__ __half g_c1kh[(size_t)NB * NH * L1 * HD];    // c1 key
__device__ __half g_c1vh[(size_t)NB * NH * L1 * HD];    // c1 val

// ---------------- helpers ----------------
__device__ __forceinline__ uint32_t h2u(__half2 h) { return *(uint32_t*)&h; }

__device__ __forceinline__ uint32_t smem_u32(const void* p) {
    uint32_t a;
    asm("{ .reg .u64 t; cvta.to.shared.u64 t, %1; cvt.u32.u64 %0, t; }"
        : "=r"(a) : "l"(p));
    return a;
}

#define MMA_F16(c, a, b0, b1)                                               \
    asm volatile(                                                           \
        "mma.sync.aligned.m16n8k16.row.col.f32.f16.f16.f32 "                \
        "{%0,%1,%2,%3}, {%4,%5,%6,%7}, {%8,%9}, {%0,%1,%2,%3};\n"           \
        : "+f"((c)[0]), "+f"((c)[1]), "+f"((c)[2]), "+f"((c)[3])            \
        : "r"((a)[0]), "r"((a)[1]), "r"((a)[2]), "r"((a)[3]),               \
          "r"(b0), "r"(b1))

__device__ __forceinline__ void ldm_x4(uint32_t& r0, uint32_t& r1,
                                       uint32_t& r2, uint32_t& r3,
                                       uint32_t addr) {
    asm volatile("ldmatrix.sync.aligned.m8n8.x4.shared.b16 {%0,%1,%2,%3}, [%4];"
                 : "=r"(r0), "=r"(r1), "=r"(r2), "=r"(r3) : "r"(addr));
}
__device__ __forceinline__ void ldm_x4_t(uint32_t& r0, uint32_t& r1,
                                         uint32_t& r2, uint32_t& r3,
                                         uint32_t addr) {
    asm volatile("ldmatrix.sync.aligned.m8n8.x4.trans.shared.b16 {%0,%1,%2,%3}, [%4];"
                 : "=r"(r0), "=r"(r1), "=r"(r2), "=r"(r3) : "r"(addr));
}

__device__ __forceinline__ void cp16h(__half* dst, const __half* src) {
    uint32_t d = (uint32_t)__cvta_generic_to_shared(dst);
    asm volatile("cp.async.cg.shared.global [%0], [%1], 16;\n" :: "r"(d), "l"(src));
}
__device__ __forceinline__ void cp16f(float* dst, const float* src) {
    uint32_t d = (uint32_t)__cvta_generic_to_shared(dst);
    asm volatile("cp.async.cg.shared.global [%0], [%1], 16;\n" :: "r"(d), "l"(src));
}
__device__ __forceinline__ void cp_commit() {
    asm volatile("cp.async.commit_group;\n");
}
template <int N> __device__ __forceinline__ void cp_wait() {
    asm volatile("cp.async.wait_group %0;\n" :: "n"(N));
}

// =====================================================================
// Fused float->fp16 conversion over ALL 8 segments (one launch).
// =====================================================================
#define SG_HID 2949120
#define SG_W   147456
#define SG_C0  589824
#define SG_C1  5898240
#define SB0 SG_HID
#define SB1 (SB0 + SG_W)
#define SB2 (SB1 + SG_W)
#define SB3 (SB2 + SG_W)
#define SB4 (SB3 + SG_C0)
#define SB5 (SB4 + SG_C0)
#define SB6 (SB5 + SG_C1)
#define SB7 (SB6 + SG_C1)

__global__ __launch_bounds__(256) void cvt_all_kernel(
    const float4* __restrict__ hid, const float4* __restrict__ wq,
    const float4* __restrict__ wk,  const float4* __restrict__ wv,
    const float4* __restrict__ c0k, const float4* __restrict__ c0v,
    const float4* __restrict__ c1k, const float4* __restrict__ c1v,
    uint2* __restrict__ d_hid, uint2* __restrict__ d_w,
    uint2* __restrict__ d_c0k, uint2* __restrict__ d_c0v,
    uint2* __restrict__ d_c1k, uint2* __restrict__ d_c1v)
{
    const int stride = gridDim.x * blockDim.x;
    for (int i = blockIdx.x * blockDim.x + threadIdx.x; i < SB7; i += stride) {
        const float4* s;
        uint2* d;
        if (i < SB0)      { s = hid + i;          d = d_hid + i; }
        else if (i < SB1) { s = wq + (i - SB0);   d = d_w + (i - SB0); }
        else if (i < SB2) { s = wk + (i - SB1);   d = d_w + SG_W + (i - SB1); }
        else if (i < SB3) { s = wv + (i - SB2);   d = d_w + 2 * SG_W + (i - SB2); }
        else if (i < SB4) { s = c0k + (i - SB3);  d = d_c0k + (i - SB3); }
        else if (i < SB5) { s = c0v + (i - SB4);  d = d_c0v + (i - SB4); }
        else if (i < SB6) { s = c1k + (i - SB5);  d = d_c1k + (i - SB5); }
        else              { s = c1v + (i - SB6);  d = d_c1v + (i - SB6); }
        float4 v = *s;
        __half2 lo = __floats2half2_rn(v.x, v.y);
        __half2 hi = __floats2half2_rn(v.z, v.w);
        uint2 o;
        o.x = h2u(lo);
        o.y = h2u(hi);
        *d = o;
    }
}

// =====================================================================
// QKV projection, fp16 mma + ldmatrix, 3-stage cp.async pipeline.
// Block 128x64, BK=32, 8 warps (4x2), warp tile 32x32; 15 KB stages.
// (round-11 proven configuration; natural-layout fp16 epilogue)
// =====================================================================
#define GLDW  20
#define A_W   (128 * GLDW)
#define B_W   (64 * GLDW)
#define STAGEW (A_W + B_W)
#define ROWB  80

__global__ __launch_bounds__(256, 3) void qkv_gemm_f16(
    const float* __restrict__ bq, const float* __restrict__ bk_,
    const float* __restrict__ bv,
    float* __restrict__ out_k, float* __restrict__ out_v)
{
    extern __shared__ uint32_t smw[];
    const uint32_t smem_b = smem_u32(smw);

    const int m0  = blockIdx.x * 128;
    const int n0g = blockIdx.y * 64;
    const int mat = n0g / NHID;
    const int n0  = n0g - mat * NHID;

    const __half* Ag = g_hidh;
    const __half* Bg = g_wh + (size_t)mat * NHID * NHID;
    const float*  bi = (mat == 0) ? bq : (mat == 1) ? bk_ : bv;

    const int tid  = threadIdx.x;
    const int lane = tid & 31;
    const int w    = tid >> 5;
    const int wm   = w & 3;
    const int wn   = w >> 2;
    const int lq   = lane & 3;
    const int lr   = lane >> 2;

    const int lg = lane >> 3, lrs = lane & 7;
    const int a_radd = (lg & 1) * 8 + lrs;
    const int a_kadd = (lg >> 1) * 8;
    const int b_radd = (lg >> 1) * 8 + lrs;
    const int b_kadd = (lg & 1) * 8;

    const int arow = tid >> 2;          // 0..63
    const int acu  = tid & 3;           // 16B unit (8 halves)

    auto load_stage = [&](int s, int k0) {
        __half* A = (__half*)smw + s * STAGEW * 2;
        __half* B = A + A_W * 2;
        cp16h(A + arow * 40 + acu * 8,
              Ag + (size_t)(m0 + arow) * NHID + k0 + acu * 8);
        cp16h(A + (arow + 64) * 40 + acu * 8,
              Ag + (size_t)(m0 + arow + 64) * NHID + k0 + acu * 8);
        cp16h(B + arow * 40 + acu * 8,
              Bg + (size_t)(n0 + arow) * NHID + k0 + acu * 8);
    };

    float acc[2][4][4];
#pragma unroll
    for (int mt = 0; mt < 2; mt++)
#pragma unroll
        for (int nt = 0; nt < 4; nt++)
#pragma unroll
            for (int i = 0; i < 4; i++) acc[mt][nt][i] = 0.f;

    auto compute = [&](int s) {
        const uint32_t Ab = smem_b + s * STAGEW * 4;
        const uint32_t Bb = Ab + A_W * 4;
#pragma unroll
        for (int ks = 0; ks < 2; ks++) {
            uint32_t af[2][4];
#pragma unroll
            for (int mt = 0; mt < 2; mt++) {
                const uint32_t addr = Ab
                    + (uint32_t)((wm * 32 + mt * 16 + a_radd) * ROWB
                                 + (ks * 16 + a_kadd) * 2);
                ldm_x4(af[mt][0], af[mt][1], af[mt][2], af[mt][3], addr);
            }
            uint32_t bf[4][2];
#pragma unroll
            for (int np = 0; np < 2; np++) {
                const uint32_t addr = Bb
                    + (uint32_t)((wn * 32 + np * 16 + b_radd) * ROWB
                                 + (ks * 16 + b_kadd) * 2);
                ldm_x4(bf[2 * np][0], bf[2 * np][1],
                       bf[2 * np + 1][0], bf[2 * np + 1][1], addr);
            }
#pragma unroll
            for (int mt = 0; mt < 2; mt++)
#pragma unroll
                for (int nt = 0; nt < 4; nt++)
                    MMA_F16(acc[mt][nt], af[mt], bf[nt][0], bf[nt][1]);
        }
    };

    load_stage(0, 0);  cp_commit();
    load_stage(1, 32); cp_commit();

    for (int it = 0; it < 24; it++) {
        if (it < 23) cp_wait<1>(); else cp_wait<0>();
        __syncthreads();
        if (it + 2 < 24) {
            load_stage((it + 2) % 3, (it + 2) * 32);
            cp_commit();
        }
        compute(it % 3);
    }

    // epilogue: bias + scatter; fp16 copies in natural layout
#pragma unroll
    for (int nt = 0; nt < 4; nt++) {
        const int ncol = n0 + wn * 32 + nt * 8 + 2 * lq;
        const float b0 = bi[ncol];
        const float b1 = bi[ncol + 1];
        const int h = ncol >> 6;
        const int d = ncol & 63;
#pragma unroll
        for (int mt = 0; mt < 2; mt++) {
            const int r = wm * 32 + mt * 16 + lr;
#pragma unroll
            for (int half = 0; half < 2; half++) {
                const int m = m0 + r + 8 * half;
                const int b = m >> 6;
                const int s = m & 63;
                const size_t bh = (size_t)b * NH + h;
                float2 v;
                v.x = acc[mt][nt][2 * half + 0] + b0;
                v.y = acc[mt][nt][2 * half + 1] + b1;
                const size_t idx = (bh * 64 + s) * 64 + d;
                if (mat == 0) {
                    *(__half2*)&g_qh[idx] = __floats2half2_rn(v.x, v.y);
                } else if (mat == 1) {
                    *(float2*)&out_k[idx] = v;
                    *(__half2*)&g_kh[idx] = __floats2half2_rn(v.x, v.y);
                } else {
                    *(float2*)&out_v[idx] = v;
                    *(__half2*)&g_vh[idx] = __floats2half2_rn(v.x, v.y);
                }
            }
        }
    }
}

// =====================================================================
// Flash cache attention, fp16 mma + ldmatrix. V consumed from NATURAL
// [j][d] layout via ldmatrix.trans (B fragments of V^T).
// =====================================================================
#define KVH_LD 72
#define KVH_TILE (64 * KVH_LD)
#define KROWB 144

__global__ __launch_bounds__(128, 4) void attn_flash_f16(
    const float* __restrict__ mask,
    float* __restrict__ outctx)
{
    extern __shared__ __half smh[];
    __half* kbuf   = smh;                       // [2][64][72]
    __half* vbuf   = kbuf + 2 * KVH_TILE;       // [2][64][72]
    float*  mask_s = (float*)(vbuf + 2 * KVH_TILE);   // [576]
    const uint32_t kb_b = smem_u32(kbuf);
    const uint32_t vb_b = smem_u32(vbuf);

    const int bh   = blockIdx.x;
    const int b    = bh / NH;
    const int h    = bh - b * NH;
    const int tid  = threadIdx.x;
    const int lane = tid & 31;
    const int w    = tid >> 5;
    const int lq   = lane & 3;
    const int lr   = lane >> 2;

    const int lg = lane >> 3, lrs = lane & 7;
    const int b_radd = (lg >> 1) * 8 + lrs;     // K (non-trans B)
    const int b_kadd = (lg & 1) * 8;
    const int v_radd = (lg & 1) * 8 + lrs;      // V (.trans): rows = k(j)-dim
    const int v_cadd = (lg >> 1) * 8;           //              cols = n(d)-dim

    const __half* c0kb = g_c0kh + ((size_t)(b & 7) * NH + h) * L0 * HD;
    const __half* c0vb = g_c0vh + ((size_t)(b & 7) * NH + h) * L0 * HD;
    const __half* c1kb = g_c1kh + (size_t)bh * L1 * HD;
    const __half* c1vb = g_c1vh + (size_t)bh * L1 * HD;
    const __half* ksb  = g_kh + (size_t)bh * NS * HD;
    const __half* vsb  = g_vh + (size_t)bh * NS * HD;

    auto ksrc_of = [&](int c) -> const __half* {
        return (c < 6) ? (c0kb + c * 64 * HD)
             : (c < 8) ? (c1kb + (c - 6) * 64 * HD) : ksb;
    };
    auto vsrc_of = [&](int c) -> const __half* {
        return (c < 6) ? (c0vb + c * 64 * HD)
             : (c < 8) ? (c1vb + (c - 6) * 64 * HD) : vsb;
    };

    auto load_tile = [&](__half* buf, const __half* src) {
        const int r  = tid >> 1;
        const int c0 = (tid & 1) * 32;
        __half* d = buf + r * KVH_LD + c0;
        const __half* s = src + (size_t)r * HD + c0;
#pragma unroll
        for (int i = 0; i < 4; i++) cp16h(d + 8 * i, s + 8 * i);
    };

    // prologue: Q -> kbuf[1]; chunk0 -> buf0; mask
    load_tile(kbuf + KVH_TILE, g_qh + (size_t)bh * NS * HD);
    cp_commit();
    load_tile(kbuf, ksrc_of(0));
    load_tile(vbuf, vsrc_of(0));
    cp_commit();
    for (int i = tid * 4; i < LTOT; i += 128 * 4)
        cp16f(mask_s + i, mask + (size_t)b * LTOT + i);
    cp_commit();

    cp_wait<2>();
    __syncthreads();

    // Q fragments via ldmatrix (A-operand shape)
    uint32_t qa[4][4];
    {
        const int a_radd = (lg & 1) * 8 + lrs;
        const int a_kadd = (lg >> 1) * 8;
        const uint32_t Qb = kb_b + KVH_TILE * 2;
#pragma unroll
        for (int ks = 0; ks < 4; ks++) {
            const uint32_t addr = Qb
                + (uint32_t)((w * 16 + a_radd) * KROWB + (ks * 16 + a_kadd) * 2);
            ldm_x4(qa[ks][0], qa[ks][1], qa[ks][2], qa[ks][3], addr);
        }
    }
    __syncthreads();

    float m0 = -1e30f, m1 = -1e30f;
    float l0 = 0.f,    l1 = 0.f;
    float o[8][4];
#pragma unroll
    for (int dt = 0; dt < 8; dt++)
#pragma unroll
        for (int i = 0; i < 4; i++) o[dt][i] = 0.f;

    for (int c = 0; c < NCHUNK; c++) {
        if (c < NCHUNK - 1) {
            load_tile(kbuf + ((c + 1) & 1) * KVH_TILE, ksrc_of(c + 1));
            load_tile(vbuf + ((c + 1) & 1) * KVH_TILE, vsrc_of(c + 1));
            cp_commit();
            cp_wait<1>();
        } else {
            cp_wait<0>();
        }
        __syncthreads();

        const uint32_t Kb = kb_b + (c & 1) * KVH_TILE * 2;
        const uint32_t Vb = vb_b + (c & 1) * KVH_TILE * 2;

        // ---- S = Q K^T ----
        float cS[8][4];
#pragma unroll
        for (int nt = 0; nt < 8; nt++)
#pragma unroll
            for (int i = 0; i < 4; i++) cS[nt][i] = 0.f;

#pragma unroll
        for (int ks = 0; ks < 4; ks++) {
#pragma unroll
            for (int np = 0; np < 4; np++) {
                uint32_t b00, b01, b10, b11;
                const uint32_t addr = Kb
                    + (uint32_t)((np * 16 + b_radd) * KROWB + (ks * 16 + b_kadd) * 2);
                ldm_x4(b00, b01, b10, b11, addr);
                MMA_F16(cS[2 * np],     qa[ks], b00, b01);
                MMA_F16(cS[2 * np + 1], qa[ks], b10, b11);
            }
        }

        // ---- mask + scale + chunk row max ----
        float cm0 = -1e30f, cm1 = -1e30f;
#pragma unroll
        for (int nt = 0; nt < 8; nt++) {
            const int col = c * 64 + nt * 8 + 2 * lq;
            const float mv0 = mask_s[col];
            const float mv1 = mask_s[col + 1];
            cS[nt][0] = cS[nt][0] * 0.125f + mv0;
            cS[nt][1] = cS[nt][1] * 0.125f + mv1;
            cS[nt][2] = cS[nt][2] * 0.125f + mv0;
            cS[nt][3] = cS[nt][3] * 0.125f + mv1;
            cm0 = fmaxf(cm0, fmaxf(cS[nt][0], cS[nt][1]));
            cm1 = fmaxf(cm1, fmaxf(cS[nt][2], cS[nt][3]));
        }
#pragma unroll
        for (int off = 1; off <= 2; off <<= 1) {
            cm0 = fmaxf(cm0, __shfl_xor_sync(0xFFFFFFFFu, cm0, off));
            cm1 = fmaxf(cm1, __shfl_xor_sync(0xFFFFFFFFu, cm1, off));
        }

        const float mn0 = fmaxf(m0, cm0);
        const float mn1 = fmaxf(m1, cm1);
        const float a0  = __expf(m0 - mn0);
        const float a1  = __expf(m1 - mn1);
        m0 = mn0; m1 = mn1;

        float s0 = 0.f, s1 = 0.f;
#pragma unroll
        for (int nt = 0; nt < 8; nt++) {
            cS[nt][0] = __expf(cS[nt][0] - mn0);
            cS[nt][1] = __expf(cS[nt][1] - mn0);
            cS[nt][2] = __expf(cS[nt][2] - mn1);
            cS[nt][3] = __expf(cS[nt][3] - mn1);
            s0 += cS[nt][0] + cS[nt][1];
            s1 += cS[nt][2] + cS[nt][3];
        }
#pragma unroll
        for (int off = 1; off <= 2; off <<= 1) {
            s0 += __shfl_xor_sync(0xFFFFFFFFu, s0, off);
            s1 += __shfl_xor_sync(0xFFFFFFFFu, s1, off);
        }
        l0 = l0 * a0 + s0;
        l1 = l1 * a1 + s1;

#pragma unroll
        for (int dt = 0; dt < 8; dt++) {
            o[dt][0] *= a0; o[dt][1] *= a0;
            o[dt][2] *= a1; o[dt][3] *= a1;
        }

        // ---- PV: in-thread P pack, V via ldmatrix.trans ----
#pragma unroll
        for (int kt = 0; kt < 4; kt++) {
            uint32_t pa[4];
            pa[0] = h2u(__floats2half2_rn(cS[2 * kt][0],     cS[2 * kt][1]));
            pa[1] = h2u(__floats2half2_rn(cS[2 * kt][2],     cS[2 * kt][3]));
            pa[2] = h2u(__floats2half2_rn(cS[2 * kt + 1][0], cS[2 * kt + 1][1]));
            pa[3] = h2u(__floats2half2_rn(cS[2 * kt + 1][2], cS[2 * kt + 1][3]));
#pragma unroll
            for (int np = 0; np < 4; np++) {
                uint32_t b00, b01, b10, b11;
                const uint32_t addr = Vb
                    + (uint32_t)((kt * 16 + v_radd) * KROWB
                                 + (np * 16 + v_cadd) * 2);
                ldm_x4_t(b00, b01, b10, b11, addr);
                MMA_F16(o[2 * np],     pa, b00, b01);
                MMA_F16(o[2 * np + 1], pa, b10, b11);
            }
        }
        __syncthreads();
    }

    // epilogue: normalize + write out[b, s, h*64 + d]
    {
        const float r0 = 1.f / l0;
        const float r1 = 1.f / l1;
        const int r = w * 16 + lr;
        float* ob0 = outctx + ((size_t)b * NS + r) * NHID + h * HD;
        float* ob1 = outctx + ((size_t)b * NS + r + 8) * NHID + h * HD;
#pragma unroll
        for (int dt = 0; dt < 8; dt++) {
            const int dcol = dt * 8 + 2 * lq;
            float2 v0, v1;
            v0.x = o[dt][0] * r0; v0.y = o[dt][1] * r0;
            v1.x = o[dt][2] * r1; v1.y = o[dt][3] * r1;
            *(float2*)&ob0[dcol] = v0;
            *(float2*)&ob1[dcol] = v1;
        }
    }
}

// =====================================================================
// Host launcher
// =====================================================================
extern "C" void kernel_launch(void* const* d_in, const int* in_sizes, int n_in,
                              void* d_out, int out_size)
{
    const float* hidden = (const float*)d_in[0];
    const float* mask   = (const float*)d_in[1];
    const float* Wq     = (const float*)d_in[2];
    const float* bq     = (const float*)d_in[3];
    const float* Wk     = (const float*)d_in[4];
    const float* bk     = (const float*)d_in[5];
    const float* Wv     = (const float*)d_in[6];
    const float* bv     = (const float*)d_in[7];
    const float* c0k    = (const float*)d_in[8];
    const float* c0v    = (const float*)d_in[9];
    const float* c1k    = (const float*)d_in[10];
    const float* c1v    = (const float*)d_in[11];

    float* out   = (float*)d_out;
    const size_t sect = (size_t)NB * NS * NHID;
    float* out_k = out + sect;
    float* out_v = out + 2 * sect;

    __half *hidh_d, *wh_d, *c0kh_d, *c0vh_d, *c1kh_d, *c1vh_d;
    cudaGetSymbolAddress((void**)&hidh_d, g_hidh);
    cudaGetSymbolAddress((void**)&wh_d,   g_wh);
    cudaGetSymbolAddress((void**)&c0kh_d, g_c0kh);
    cudaGetSymbolAddress((void**)&c0vh_d, g_c0vh);
    cudaGetSymbolAddress((void**)&c1kh_d, g_c1kh);
    cudaGetSymbolAddress((void**)&c1vh_d, g_c1vh);

    const int gemm_smem = 3 * STAGEW * 4;                 // 46080
    const int attn_smem = 4 * KVH_TILE * 2 + LTOT * 4;    // 39168

    cudaFuncSetAttribute(qkv_gemm_f16,
                         cudaFuncAttributeMaxDynamicSharedMemorySize, gemm_smem);
    cudaFuncSetAttribute(attn_flash_f16,
                         cudaFuncAttributeMaxDynamicSharedMemorySize, attn_smem);

    // preprocessing: ONE fused convert launch (all 8 tensors)
    cvt_all_kernel<<<4096, 256>>>(
        (const float4*)hidden, (const float4*)Wq, (const float4*)Wk,
        (const float4*)Wv, (const float4*)c0k, (const float4*)c0v,
        (const float4*)c1k, (const float4*)c1v,
        (uint2*)hidh_d, (uint2*)wh_d, (uint2*)c0kh_d, (uint2*)c0vh_d,
        (uint2*)c1kh_d, (uint2*)c1vh_d);

    dim3 ggrid(NB * NS / 128, 3 * NHID / 64);       // (120, 36)
    qkv_gemm_f16<<<ggrid, 256, gemm_smem>>>(bq, bk, bv, out_k, out_v);

    attn_flash_f16<<<NB * NH, 128, attn_smem>>>(mask, out);
}

// round 14
// speedup vs baseline: 1.1534x; 1.0389x over previous
#include <cuda_runtime.h>
#include <cuda_fp16.h>
#include <cstdint>

// ---------------- problem constants (fixed by the dataset) ----------------
#define NB    240
#define NS    64
#define NHID  768
#define NH    12
#define HD    64
#define L0    384
#define L1    128
#define LTOT  576
#define NCHUNK 9

// device-global scratch (allocation-free); all fp16, NATURAL layouts
__device__ __half g_hidh[(size_t)NB * NS * NHID];       // hidden
__device__ __half g_wh  [(size_t)3 * NHID * NHID];      // Wq|Wk|Wv
__device__ __half g_qh  [(size_t)NB * NH * NS * HD];    // q [bh][s][d]
__device__ __half g_kh  [(size_t)NB * NH * NS * HD];    // k [bh][s][d]
__device__ __half g_vh  [(size_t)NB * NH * NS * HD];    // v [bh][s][d]
__device__ __half g_c0kh[(size_t)8 * NH * L0 * HD];     // c0 key [g][j][d]
__device__ __half g_c0vh[(size_t)8 * NH * L0 * HD];     // c0 val [g][j][d]

// ---------------- helpers ----------------
__device__ __forceinline__ uint32_t h2u(__half2 h) { return *(uint32_t*)&h; }

__device__ __forceinline__ uint32_t smem_u32(const void* p) {
    uint32_t a;
    asm("{ .reg .u64 t; cvta.to.shared.u64 t, %1; cvt.u32.u64 %0, t; }"
        : "=r"(a) : "l"(p));
    return a;
}

#define MMA_F16(c, a, b0, b1)                                               \
    asm volatile(                                                           \
        "mma.sync.aligned.m16n8k16.row.col.f32.f16.f16.f32 "                \
        "{%0,%1,%2,%3}, {%4,%5,%6,%7}, {%8,%9}, {%0,%1,%2,%3};\n"           \
        : "+f"((c)[0]), "+f"((c)[1]), "+f"((c)[2]), "+f"((c)[3])            \
        : "r"((a)[0]), "r"((a)[1]), "r"((a)[2]), "r"((a)[3]),               \
          "r"(b0), "r"(b1))

__device__ __forceinline__ void ldm_x4(uint32_t& r0, uint32_t& r1,
                                       uint32_t& r2, uint32_t& r3,
                                       uint32_t addr) {
    asm volatile("ldmatrix.sync.aligned.m8n8.x4.shared.b16 {%0,%1,%2,%3}, [%4];"
                 : "=r"(r0), "=r"(r1), "=r"(r2), "=r"(r3) : "r"(addr));
}
__device__ __forceinline__ void ldm_x4_t(uint32_t& r0, uint32_t& r1,
                                         uint32_t& r2, uint32_t& r3,
                                         uint32_t addr) {
    asm volatile("ldmatrix.sync.aligned.m8n8.x4.trans.shared.b16 {%0,%1,%2,%3}, [%4];"
                 : "=r"(r0), "=r"(r1), "=r"(r2), "=r"(r3) : "r"(addr));
}

__device__ __forceinline__ void cp16h(__half* dst, const __half* src) {
    uint32_t d = (uint32_t)__cvta_generic_to_shared(dst);
    asm volatile("cp.async.cg.shared.global [%0], [%1], 16;\n" :: "r"(d), "l"(src));
}
__device__ __forceinline__ void cp16f(float* dst, const float* src) {
    uint32_t d = (uint32_t)__cvta_generic_to_shared(dst);
    asm volatile("cp.async.cg.shared.global [%0], [%1], 16;\n" :: "r"(d), "l"(src));
}
__device__ __forceinline__ void cp_commit() {
    asm volatile("cp.async.commit_group;\n");
}
template <int N> __device__ __forceinline__ void cp_wait() {
    asm volatile("cp.async.wait_group %0;\n" :: "n"(N));
}

// =====================================================================
// Fused float->fp16 conversion: hidden | Wq|Wk|Wv | c0k | c0v.
// (c1k/c1v are single-use -> converted inline by the attention kernel.)
// =====================================================================
#define SG_HID 2949120
#define SG_W   147456
#define SG_C0  589824
#define SB0 SG_HID
#define SB1 (SB0 + SG_W)
#define SB2 (SB1 + SG_W)
#define SB3 (SB2 + SG_W)
#define SB4 (SB3 + SG_C0)
#define SB5 (SB4 + SG_C0)

__global__ __launch_bounds__(256) void cvt_all_kernel(
    const float4* __restrict__ hid, const float4* __restrict__ wq,
    const float4* __restrict__ wk,  const float4* __restrict__ wv,
    const float4* __restrict__ c0k, const float4* __restrict__ c0v,
    uint2* __restrict__ d_hid, uint2* __restrict__ d_w,
    uint2* __restrict__ d_c0k, uint2* __restrict__ d_c0v)
{
    const int stride = gridDim.x * blockDim.x;
    for (int i = blockIdx.x * blockDim.x + threadIdx.x; i < SB5; i += stride) {
        const float4* s;
        uint2* d;
        if (i < SB0)      { s = hid + i;          d = d_hid + i; }
        else if (i < SB1) { s = wq + (i - SB0);   d = d_w + (i - SB0); }
        else if (i < SB2) { s = wk + (i - SB1);   d = d_w + SG_W + (i - SB1); }
        else if (i < SB3) { s = wv + (i - SB2);   d = d_w + 2 * SG_W + (i - SB2); }
        else if (i < SB4) { s = c0k + (i - SB3);  d = d_c0k + (i - SB3); }
        else              { s = c0v + (i - SB4);  d = d_c0v + (i - SB4); }
        float4 v = *s;
        __half2 lo = __floats2half2_rn(v.x, v.y);
        __half2 hi = __floats2half2_rn(v.z, v.w);
        uint2 o;
        o.x = h2u(lo);
        o.y = h2u(hi);
        *d = o;
    }
}

// =====================================================================
// QKV projection, fp16 mma + ldmatrix, 3-stage cp.async pipeline.
// Block 128x64, BK=32, 8 warps (4x2), warp tile 32x32; 15 KB stages.
// =====================================================================
#define GLDW  20
#define A_W   (128 * GLDW)
#define B_W   (64 * GLDW)
#define STAGEW (A_W + B_W)
#define ROWB  80

__global__ __launch_bounds__(256, 3) void qkv_gemm_f16(
    const float* __restrict__ bq, const float* __restrict__ bk_,
    const float* __restrict__ bv,
    float* __restrict__ out_k, float* __restrict__ out_v)
{
    extern __shared__ uint32_t smw[];
    const uint32_t smem_b = smem_u32(smw);

    const int m0  = blockIdx.x * 128;
    const int n0g = blockIdx.y * 64;
    const int mat = n0g / NHID;
    const int n0  = n0g - mat * NHID;

    const __half* Ag = g_hidh;
    const __half* Bg = g_wh + (size_t)mat * NHID * NHID;
    const float*  bi = (mat == 0) ? bq : (mat == 1) ? bk_ : bv;

    const int tid  = threadIdx.x;
    const int lane = tid & 31;
    const int w    = tid >> 5;
    const int wm   = w & 3;
    const int wn   = w >> 2;
    const int lq   = lane & 3;
    const int lr   = lane >> 2;

    const int lg = lane >> 3, lrs = lane & 7;
    const int a_radd = (lg & 1) * 8 + lrs;
    const int a_kadd = (lg >> 1) * 8;
    const int b_radd = (lg >> 1) * 8 + lrs;
    const int b_kadd = (lg & 1) * 8;

    const int arow = tid >> 2;          // 0..63
    const int acu  = tid & 3;           // 16B unit (8 halves)

    auto load_stage = [&](int s, int k0) {
        __half* A = (__half*)smw + s * STAGEW * 2;
        __half* B = A + A_W * 2;
        cp16h(A + arow * 40 + acu * 8,
              Ag + (size_t)(m0 + arow) * NHID + k0 + acu * 8);
        cp16h(A + (arow + 64) * 40 + acu * 8,
              Ag + (size_t)(m0 + arow + 64) * NHID + k0 + acu * 8);
        cp16h(B + arow * 40 + acu * 8,
              Bg + (size_t)(n0 + arow) * NHID + k0 + acu * 8);
    };

    float acc[2][4][4];
#pragma unroll
    for (int mt = 0; mt < 2; mt++)
#pragma unroll
        for (int nt = 0; nt < 4; nt++)
#pragma unroll
            for (int i = 0; i < 4; i++) acc[mt][nt][i] = 0.f;

    auto compute = [&](int s) {
        const uint32_t Ab = smem_b + s * STAGEW * 4;
        const uint32_t Bb = Ab + A_W * 4;
#pragma unroll
        for (int ks = 0; ks < 2; ks++) {
            uint32_t af[2][4];
#pragma unroll
            for (int mt = 0; mt < 2; mt++) {
                const uint32_t addr = Ab
                    + (uint32_t)((wm * 32 + mt * 16 + a_radd) * ROWB
                                 + (ks * 16 + a_kadd) * 2);
                ldm_x4(af[mt][0], af[mt][1], af[mt][2], af[mt][3], addr);
            }
            uint32_t bf[4][2];
#pragma unroll
            for (int np = 0; np < 2; np++) {
                const uint32_t addr = Bb
                    + (uint32_t)((wn * 32 + np * 16 + b_radd) * ROWB
                                 + (ks * 16 + b_kadd) * 2);
                ldm_x4(bf[2 * np][0], bf[2 * np][1],
                       bf[2 * np + 1][0], bf[2 * np + 1][1], addr);
            }
#pragma unroll
            for (int mt = 0; mt < 2; mt++)
#pragma unroll
                for (int nt = 0; nt < 4; nt++)
                    MMA_F16(acc[mt][nt], af[mt], bf[nt][0], bf[nt][1]);
        }
    };

    load_stage(0, 0);  cp_commit();
    load_stage(1, 32); cp_commit();

    for (int it = 0; it < 24; it++) {
        if (it < 23) cp_wait<1>(); else cp_wait<0>();
        __syncthreads();
        if (it + 2 < 24) {
            load_stage((it + 2) % 3, (it + 2) * 32);
            cp_commit();
        }
        compute(it % 3);
    }

    // epilogue: bias + scatter; fp16 copies in natural layout
#pragma unroll
    for (int nt = 0; nt < 4; nt++) {
        const int ncol = n0 + wn * 32 + nt * 8 + 2 * lq;
        const float b0 = bi[ncol];
        const float b1 = bi[ncol + 1];
        const int h = ncol >> 6;
        const int d = ncol & 63;
#pragma unroll
        for (int mt = 0; mt < 2; mt++) {
            const int r = wm * 32 + mt * 16 + lr;
#pragma unroll
            for (int half = 0; half < 2; half++) {
                const int m = m0 + r + 8 * half;
                const int b = m >> 6;
                const int s = m & 63;
                const size_t bh = (size_t)b * NH + h;
                float2 v;
                v.x = acc[mt][nt][2 * half + 0] + b0;
                v.y = acc[mt][nt][2 * half + 1] + b1;
                const size_t idx = (bh * 64 + s) * 64 + d;
                if (mat == 0) {
                    *(__half2*)&g_qh[idx] = __floats2half2_rn(v.x, v.y);
                } else if (mat == 1) {
                    *(float2*)&out_k[idx] = v;
                    *(__half2*)&g_kh[idx] = __floats2half2_rn(v.x, v.y);
                } else {
                    *(float2*)&out_v[idx] = v;
                    *(__half2*)&g_vh[idx] = __floats2half2_rn(v.x, v.y);
                }
            }
        }
    }
}

// =====================================================================
// Flash cache attention, fp16 mma + ldmatrix. V consumed from natural
// [j][d] layout via ldmatrix.trans. Chunks 6,7 (c1) converted inline
// from fp32 (single-use data: no pre-conversion pass).
// =====================================================================
#define KVH_LD 72
#define KVH_TILE (64 * KVH_LD)
#define KROWB 144

__global__ __launch_bounds__(128, 4) void attn_flash_f16(
    const float* __restrict__ mask,
    const float* __restrict__ c1k, const float* __restrict__ c1v,
    float* __restrict__ outctx)
{
    extern __shared__ __half smh[];
    __half* kbuf   = smh;                       // [2][64][72]
    __half* vbuf   = kbuf + 2 * KVH_TILE;       // [2][64][72]
    float*  mask_s = (float*)(vbuf + 2 * KVH_TILE);   // [576]
    const uint32_t kb_b = smem_u32(kbuf);
    const uint32_t vb_b = smem_u32(vbuf);

    const int bh   = blockIdx.x;
    const int b    = bh / NH;
    const int h    = bh - b * NH;
    const int tid  = threadIdx.x;
    const int lane = tid & 31;
    const int w    = tid >> 5;
    const int lq   = lane & 3;
    const int lr   = lane >> 2;

    const int lg = lane >> 3, lrs = lane & 7;
    const int b_radd = (lg >> 1) * 8 + lrs;     // K (non-trans B)
    const int b_kadd = (lg & 1) * 8;
    const int v_radd = (lg & 1) * 8 + lrs;      // V (.trans)
    const int v_cadd = (lg >> 1) * 8;

    const __half* c0kb = g_c0kh + ((size_t)(b & 7) * NH + h) * L0 * HD;
    const __half* c0vb = g_c0vh + ((size_t)(b & 7) * NH + h) * L0 * HD;
    const float*  c1kf = c1k + (size_t)bh * L1 * HD;
    const float*  c1vf = c1v + (size_t)bh * L1 * HD;
    const __half* ksb  = g_kh + (size_t)bh * NS * HD;
    const __half* vsb  = g_vh + (size_t)bh * NS * HD;

    // fp16 sources for chunks 0-5 and 8 (6,7 handled inline from fp32)
    auto ksrc_of = [&](int c) -> const __half* {
        return (c < 6) ? (c0kb + c * 64 * HD) : ksb;
    };
    auto vsrc_of = [&](int c) -> const __half* {
        return (c < 6) ? (c0vb + c * 64 * HD) : vsb;
    };

    auto load_tile = [&](__half* buf, const __half* src) {
        const int r  = tid >> 1;
        const int c0 = (tid & 1) * 32;
        __half* d = buf + r * KVH_LD + c0;
        const __half* s = src + (size_t)r * HD + c0;
#pragma unroll
        for (int i = 0; i < 4; i++) cp16h(d + 8 * i, s + 8 * i);
    };

    // inline fp32 -> fp16 tile convert (c1 chunks): LDG float4 -> STS uint4
    auto cvt_tile = [&](__half* buf, const float* src) {
        const int r  = tid >> 1;
        const int cb = (tid & 1) * 32;
        const float* s = src + (size_t)r * HD + cb;
        __half* d = buf + r * KVH_LD + cb;
#pragma unroll
        for (int i = 0; i < 4; i++) {
            float4 v0 = *(const float4*)(s + 8 * i);
            float4 v1 = *(const float4*)(s + 8 * i + 4);
            uint4 o;
            o.x = h2u(__floats2half2_rn(v0.x, v0.y));
            o.y = h2u(__floats2half2_rn(v0.z, v0.w));
            o.z = h2u(__floats2half2_rn(v1.x, v1.y));
            o.w = h2u(__floats2half2_rn(v1.z, v1.w));
            *(uint4*)(d + 8 * i) = o;
        }
    };

    // prologue: Q -> kbuf[1]; chunk0 -> buf0; mask
    load_tile(kbuf + KVH_TILE, g_qh + (size_t)bh * NS * HD);
    cp_commit();
    load_tile(kbuf, ksrc_of(0));
    load_tile(vbuf, vsrc_of(0));
    cp_commit();
    for (int i = tid * 4; i < LTOT; i += 128 * 4)
        cp16f(mask_s + i, mask + (size_t)b * LTOT + i);
    cp_commit();

    cp_wait<2>();
    __syncthreads();

    // Q fragments via ldmatrix (A-operand shape)
    uint32_t qa[4][4];
    {
        const int a_radd = (lg & 1) * 8 + lrs;
        const int a_kadd = (lg >> 1) * 8;
        const uint32_t Qb = kb_b + KVH_TILE * 2;
#pragma unroll
        for (int ks = 0; ks < 4; ks++) {
            const uint32_t addr = Qb
                + (uint32_t)((w * 16 + a_radd) * KROWB + (ks * 16 + a_kadd) * 2);
            ldm_x4(qa[ks][0], qa[ks][1], qa[ks][2], qa[ks][3], addr);
        }
    }
    __syncthreads();

    float m0 = -1e30f, m1 = -1e30f;
    float l0 = 0.f,    l1 = 0.f;
    float o[8][4];
#pragma unroll
    for (int dt = 0; dt < 8; dt++)
#pragma unroll
        for (int i = 0; i < 4; i++) o[dt][i] = 0.f;

    for (int c = 0; c < NCHUNK; c++) {
        const int nx = c + 1;
        if (nx < NCHUNK && nx != 6 && nx != 7) {
            load_tile(kbuf + (nx & 1) * KVH_TILE, ksrc_of(nx));
            load_tile(vbuf + (nx & 1) * KVH_TILE, vsrc_of(nx));
        }
        cp_commit();                       // (possibly empty group)
        if (c < NCHUNK - 1) cp_wait<1>(); else cp_wait<0>();
        __syncthreads();

        if (c == 6 || c == 7) {            // c1 chunks: convert inline
            cvt_tile(kbuf + (c & 1) * KVH_TILE, c1kf + (c - 6) * 64 * HD);
            cvt_tile(vbuf + (c & 1) * KVH_TILE, c1vf + (c - 6) * 64 * HD);
            __syncthreads();
        }

        const uint32_t Kb = kb_b + (c & 1) * KVH_TILE * 2;
        const uint32_t Vb = vb_b + (c & 1) * KVH_TILE * 2;

        // ---- S = Q K^T ----
        float cS[8][4];
#pragma unroll
        for (int nt = 0; nt < 8; nt++)
#pragma unroll
            for (int i = 0; i < 4; i++) cS[nt][i] = 0.f;

#pragma unroll
        for (int ks = 0; ks < 4; ks++) {
#pragma unroll
            for (int np = 0; np < 4; np++) {
                uint32_t b00, b01, b10, b11;
                const uint32_t addr = Kb
                    + (uint32_t)((np * 16 + b_radd) * KROWB + (ks * 16 + b_kadd) * 2);
                ldm_x4(b00, b01, b10, b11, addr);
                MMA_F16(cS[2 * np],     qa[ks], b00, b01);
                MMA_F16(cS[2 * np + 1], qa[ks], b10, b11);
            }
        }

        // ---- mask + scale + chunk row max ----
        float cm0 = -1e30f, cm1 = -1e30f;
#pragma unroll
        for (int nt = 0; nt < 8; nt++) {
            const int col = c * 64 + nt * 8 + 2 * lq;
            const float mv0 = mask_s[col];
            const float mv1 = mask_s[col + 1];
            cS[nt][0] = cS[nt][0] * 0.125f + mv0;
            cS[nt][1] = cS[nt][1] * 0.125f + mv1;
            cS[nt][2] = cS[nt][2] * 0.125f + mv0;
            cS[nt][3] = cS[nt][3] * 0.125f + mv1;
            cm0 = fmaxf(cm0, fmaxf(cS[nt][0], cS[nt][1]));
            cm1 = fmaxf(cm1, fmaxf(cS[nt][2], cS[nt][3]));
        }
#pragma unroll
        for (int off = 1; off <= 2; off <<= 1) {
            cm0 = fmaxf(cm0, __shfl_xor_sync(0xFFFFFFFFu, cm0, off));
            cm1 = fmaxf(cm1, __shfl_xor_sync(0xFFFFFFFFu, cm1, off));
        }

        const float mn0 = fmaxf(m0, cm0);
        const float mn1 = fmaxf(m1, cm1);
        const float a0  = __expf(m0 - mn0);
        const float a1  = __expf(m1 - mn1);
        m0 = mn0; m1 = mn1;

        float s0 = 0.f, s1 = 0.f;
#pragma unroll
        for (int nt = 0; nt < 8; nt++) {
            cS[nt][0] = __expf(cS[nt][0] - mn0);
            cS[nt][1] = __expf(cS[nt][1] - mn0);
            cS[nt][2] = __expf(cS[nt][2] - mn1);
            cS[nt][3] = __expf(cS[nt][3] - mn1);
            s0 += cS[nt][0] + cS[nt][1];
            s1 += cS[nt][2] + cS[nt][3];
        }
#pragma unroll
        for (int off = 1; off <= 2; off <<= 1) {
            s0 += __shfl_xor_sync(0xFFFFFFFFu, s0, off);
            s1 += __shfl_xor_sync(0xFFFFFFFFu, s1, off);
        }
        l0 = l0 * a0 + s0;
        l1 = l1 * a1 + s1;

#pragma unroll
        for (int dt = 0; dt < 8; dt++) {
            o[dt][0] *= a0; o[dt][1] *= a0;
            o[dt][2] *= a1; o[dt][3] *= a1;
        }

        // ---- PV: in-thread P pack, V via ldmatrix.trans ----
#pragma unroll
        for (int kt = 0; kt < 4; kt++) {
            uint32_t pa[4];
            pa[0] = h2u(__floats2half2_rn(cS[2 * kt][0],     cS[2 * kt][1]));
            pa[1] = h2u(__floats2half2_rn(cS[2 * kt][2],     cS[2 * kt][3]));
            pa[2] = h2u(__floats2half2_rn(cS[2 * kt + 1][0], cS[2 * kt + 1][1]));
            pa[3] = h2u(__floats2half2_rn(cS[2 * kt + 1][2], cS[2 * kt + 1][3]));
#pragma unroll
            for (int np = 0; np < 4; np++) {
                uint32_t b00, b01, b10, b11;
                const uint32_t addr = Vb
                    + (uint32_t)((kt * 16 + v_radd) * KROWB
                                 + (np * 16 + v_cadd) * 2);
                ldm_x4_t(b00, b01, b10, b11, addr);
                MMA_F16(o[2 * np],     pa, b00, b01);
                MMA_F16(o[2 * np + 1], pa, b10, b11);
            }
        }
        __syncthreads();
    }

    // epilogue: normalize + write out[b, s, h*64 + d]
    {
        const float r0 = 1.f / l0;
        const float r1 = 1.f / l1;
        const int r = w * 16 + lr;
        float* ob0 = outctx + ((size_t)b * NS + r) * NHID + h * HD;
        float* ob1 = outctx + ((size_t)b * NS + r + 8) * NHID + h * HD;
#pragma unroll
        for (int dt = 0; dt < 8; dt++) {
            const int dcol = dt * 8 + 2 * lq;
            float2 v0, v1;
            v0.x = o[dt][0] * r0; v0.y = o[dt][1] * r0;
            v1.x = o[dt][2] * r1; v1.y = o[dt][3] * r1;
            *(float2*)&ob0[dcol] = v0;
            *(float2*)&ob1[dcol] = v1;
        }
    }
}

// =====================================================================
// Host launcher
// =====================================================================
extern "C" void kernel_launch(void* const* d_in, const int* in_sizes, int n_in,
                              void* d_out, int out_size)
{
    const float* hidden = (const float*)d_in[0];
    const float* mask   = (const float*)d_in[1];
    const float* Wq     = (const float*)d_in[2];
    const float* bq     = (const float*)d_in[3];
    const float* Wk     = (const float*)d_in[4];
    const float* bk     = (const float*)d_in[5];
    const float* Wv     = (const float*)d_in[6];
    const float* bv     = (const float*)d_in[7];
    const float* c0k    = (const float*)d_in[8];
    const float* c0v    = (const float*)d_in[9];
    const float* c1k    = (const float*)d_in[10];
    const float* c1v    = (const float*)d_in[11];

    float* out   = (float*)d_out;
    const size_t sect = (size_t)NB * NS * NHID;
    float* out_k = out + sect;
    float* out_v = out + 2 * sect;

    __half *hidh_d, *wh_d, *c0kh_d, *c0vh_d;
    cudaGetSymbolAddress((void**)&hidh_d, g_hidh);
    cudaGetSymbolAddress((void**)&wh_d,   g_wh);
    cudaGetSymbolAddress((void**)&c0kh_d, g_c0kh);
    cudaGetSymbolAddress((void**)&c0vh_d, g_c0vh);

    const int gemm_smem = 3 * STAGEW * 4;                 // 46080
    const int attn_smem = 4 * KVH_TILE * 2 + LTOT * 4;    // 39168

    cudaFuncSetAttribute(qkv_gemm_f16,
                         cudaFuncAttributeMaxDynamicSharedMemorySize, gemm_smem);
    cudaFuncSetAttribute(attn_flash_f16,
                         cudaFuncAttributeMaxDynamicSharedMemorySize, attn_smem);

    // preprocessing: one fused convert launch (hidden, W, c0 only)
    cvt_all_kernel<<<4096, 256>>>(
        (const float4*)hidden, (const float4*)Wq, (const float4*)Wk,
        (const float4*)Wv, (const float4*)c0k, (const float4*)c0v,
        (uint2*)hidh_d, (uint2*)wh_d, (uint2*)c0kh_d, (uint2*)c0vh_d);

    dim3 ggrid(NB * NS / 128, 3 * NHID / 64);       // (120, 36)
    qkv_gemm_f16<<<ggrid, 256, gemm_smem>>>(bq, bk, bv, out_k, out_v);

    attn_flash_f16<<<NB * NH, 128, attn_smem>>>(mask, c1k, c1v, out);
}

// round 15
// speedup vs baseline: 1.1769x; 1.0204x over previous
#include <cuda_runtime.h>
#include <cuda_fp16.h>
#include <cstdint>

// ---------------- problem constants (fixed by the dataset) ----------------
#define NB    240
#define NS    64
#define NHID  768
#define NH    12
#define HD    64
#define L0    384
#define L1    128
#define LTOT  576
#define NCHUNK 9

// device-global scratch (allocation-free); all fp16, NATURAL layouts
__device__ __half g_hidh[(size_t)NB * NS * NHID];       // hidden
__device__ __half g_wh  [(size_t)3 * NHID * NHID];      // Wq|Wk|Wv
__device__ __half g_qh  [(size_t)NB * NH * NS * HD];    // q [bh][s][d]
__device__ __half g_kh  [(size_t)NB * NH * NS * HD];    // k [bh][s][d]
__device__ __half g_vh  [(size_t)NB * NH * NS * HD];    // v [bh][s][d]
__device__ __half g_c0kh[(size_t)8 * NH * L0 * HD];     // c0 key [g][j][d]
__device__ __half g_c0vh[(size_t)8 * NH * L0 * HD];     // c0 val [g][j][d]

// ---------------- helpers ----------------
__device__ __forceinline__ uint32_t h2u(__half2 h) { return *(uint32_t*)&h; }

__device__ __forceinline__ uint32_t smem_u32(const void* p) {
    uint32_t a;
    asm("{ .reg .u64 t; cvta.to.shared.u64 t, %1; cvt.u32.u64 %0, t; }"
        : "=r"(a) : "l"(p));
    return a;
}

#define MMA_F16(c, a, b0, b1)                                               \
    asm volatile(                                                           \
        "mma.sync.aligned.m16n8k16.row.col.f32.f16.f16.f32 "                \
        "{%0,%1,%2,%3}, {%4,%5,%6,%7}, {%8,%9}, {%0,%1,%2,%3};\n"           \
        : "+f"((c)[0]), "+f"((c)[1]), "+f"((c)[2]), "+f"((c)[3])            \
        : "r"((a)[0]), "r"((a)[1]), "r"((a)[2]), "r"((a)[3]),               \
          "r"(b0), "r"(b1))

__device__ __forceinline__ void ldm_x4(uint32_t& r0, uint32_t& r1,
                                       uint32_t& r2, uint32_t& r3,
                                       uint32_t addr) {
    asm volatile("ldmatrix.sync.aligned.m8n8.x4.shared.b16 {%0,%1,%2,%3}, [%4];"
                 : "=r"(r0), "=r"(r1), "=r"(r2), "=r"(r3) : "r"(addr));
}
__device__ __forceinline__ void ldm_x4_t(uint32_t& r0, uint32_t& r1,
                                         uint32_t& r2, uint32_t& r3,
                                         uint32_t addr) {
    asm volatile("ldmatrix.sync.aligned.m8n8.x4.trans.shared.b16 {%0,%1,%2,%3}, [%4];"
                 : "=r"(r0), "=r"(r1), "=r"(r2), "=r"(r3) : "r"(addr));
}

__device__ __forceinline__ void cp16h(__half* dst, const __half* src) {
    uint32_t d = (uint32_t)__cvta_generic_to_shared(dst);
    asm volatile("cp.async.cg.shared.global [%0], [%1], 16;\n" :: "r"(d), "l"(src));
}
__device__ __forceinline__ void cp16f(float* dst, const float* src) {
    uint32_t d = (uint32_t)__cvta_generic_to_shared(dst);
    asm volatile("cp.async.cg.shared.global [%0], [%1], 16;\n" :: "r"(d), "l"(src));
}
__device__ __forceinline__ void cp_commit() {
    asm volatile("cp.async.commit_group;\n");
}
template <int N> __device__ __forceinline__ void cp_wait() {
    asm volatile("cp.async.wait_group %0;\n" :: "n"(N));
}

// =====================================================================
// Fused float->fp16 conversion: hidden | Wq|Wk|Wv | c0k | c0v.
// (c1k/c1v are single-use -> converted inline by the attention kernel.)
// =====================================================================
#define SG_HID 2949120
#define SG_W   147456
#define SG_C0  589824
#define SB0 SG_HID
#define SB1 (SB0 + SG_W)
#define SB2 (SB1 + SG_W)
#define SB3 (SB2 + SG_W)
#define SB4 (SB3 + SG_C0)
#define SB5 (SB4 + SG_C0)

__global__ __launch_bounds__(256) void cvt_all_kernel(
    const float4* __restrict__ hid, const float4* __restrict__ wq,
    const float4* __restrict__ wk,  const float4* __restrict__ wv,
    const float4* __restrict__ c0k, const float4* __restrict__ c0v,
    uint2* __restrict__ d_hid, uint2* __restrict__ d_w,
    uint2* __restrict__ d_c0k, uint2* __restrict__ d_c0v)
{
    const int stride = gridDim.x * blockDim.x;
    for (int i = blockIdx.x * blockDim.x + threadIdx.x; i < SB5; i += stride) {
        const float4* s;
        uint2* d;
        if (i < SB0)      { s = hid + i;          d = d_hid + i; }
        else if (i < SB1) { s = wq + (i - SB0);   d = d_w + (i - SB0); }
        else if (i < SB2) { s = wk + (i - SB1);   d = d_w + SG_W + (i - SB1); }
        else if (i < SB3) { s = wv + (i - SB2);   d = d_w + 2 * SG_W + (i - SB2); }
        else if (i < SB4) { s = c0k + (i - SB3);  d = d_c0k + (i - SB3); }
        else              { s = c0v + (i - SB4);  d = d_c0v + (i - SB4); }
        float4 v = *s;
        __half2 lo = __floats2half2_rn(v.x, v.y);
        __half2 hi = __floats2half2_rn(v.z, v.w);
        uint2 o;
        o.x = h2u(lo);
        o.y = h2u(hi);
        *d = o;
    }
}

// =====================================================================
// QKV projection, fp16 mma + ldmatrix, 3-stage cp.async pipeline.
// Block tile 128x128, BK=32, 512 threads = 16 warps (4x4), warp tile
// 32x32 (proven shape); 20 KB stages; launch_bounds(512,2) -> 32
// warps/SM. Halves A L2 re-read traffic vs N-tile 64.
// =====================================================================
#define GLDW  20
#define A_W   (128 * GLDW)
#define B_W   (128 * GLDW)
#define STAGEW (A_W + B_W)
#define ROWB  80

__global__ __launch_bounds__(512, 2) void qkv_gemm_f16(
    const float* __restrict__ bq, const float* __restrict__ bk_,
    const float* __restrict__ bv,
    float* __restrict__ out_k, float* __restrict__ out_v)
{
    extern __shared__ uint32_t smw[];
    const uint32_t smem_b = smem_u32(smw);

    const int m0  = blockIdx.x * 128;
    const int n0g = blockIdx.y * 128;
    const int mat = n0g / NHID;
    const int n0  = n0g - mat * NHID;

    const __half* Ag = g_hidh;
    const __half* Bg = g_wh + (size_t)mat * NHID * NHID;
    const float*  bi = (mat == 0) ? bq : (mat == 1) ? bk_ : bv;

    const int tid  = threadIdx.x;
    const int lane = tid & 31;
    const int w    = tid >> 5;          // 0..15
    const int wm   = w & 3;             // m band (32 rows)
    const int wn   = w >> 2;            // n band (32 cols, 0..3)
    const int lq   = lane & 3;
    const int lr   = lane >> 2;

    const int lg = lane >> 3, lrs = lane & 7;
    const int a_radd = (lg & 1) * 8 + lrs;
    const int a_kadd = (lg >> 1) * 8;
    const int b_radd = (lg >> 1) * 8 + lrs;
    const int b_kadd = (lg & 1) * 8;

    // staging: A 512 x 16B units, B 512 units; 1 of each per thread
    const int arow = tid >> 2;          // 0..127
    const int acu  = tid & 3;           // 16B unit (8 halves)

    auto load_stage = [&](int s, int k0) {
        __half* A = (__half*)smw + s * STAGEW * 2;
        __half* B = A + A_W * 2;
        cp16h(A + arow * 40 + acu * 8,
              Ag + (size_t)(m0 + arow) * NHID + k0 + acu * 8);
        cp16h(B + arow * 40 + acu * 8,
              Bg + (size_t)(n0 + arow) * NHID + k0 + acu * 8);
    };

    float acc[2][4][4];
#pragma unroll
    for (int mt = 0; mt < 2; mt++)
#pragma unroll
        for (int nt = 0; nt < 4; nt++)
#pragma unroll
            for (int i = 0; i < 4; i++) acc[mt][nt][i] = 0.f;

    auto compute = [&](int s) {
        const uint32_t Ab = smem_b + s * STAGEW * 4;
        const uint32_t Bb = Ab + A_W * 4;
#pragma unroll
        for (int ks = 0; ks < 2; ks++) {
            uint32_t af[2][4];
#pragma unroll
            for (int mt = 0; mt < 2; mt++) {
                const uint32_t addr = Ab
                    + (uint32_t)((wm * 32 + mt * 16 + a_radd) * ROWB
                                 + (ks * 16 + a_kadd) * 2);
                ldm_x4(af[mt][0], af[mt][1], af[mt][2], af[mt][3], addr);
            }
            uint32_t bf[4][2];
#pragma unroll
            for (int np = 0; np < 2; np++) {
                const uint32_t addr = Bb
                    + (uint32_t)((wn * 32 + np * 16 + b_radd) * ROWB
                                 + (ks * 16 + b_kadd) * 2);
                ldm_x4(bf[2 * np][0], bf[2 * np][1],
                       bf[2 * np + 1][0], bf[2 * np + 1][1], addr);
            }
#pragma unroll
            for (int mt = 0; mt < 2; mt++)
#pragma unroll
                for (int nt = 0; nt < 4; nt++)
                    MMA_F16(acc[mt][nt], af[mt], bf[nt][0], bf[nt][1]);
        }
    };

    load_stage(0, 0);  cp_commit();
    load_stage(1, 32); cp_commit();

    for (int it = 0; it < 24; it++) {
        if (it < 23) cp_wait<1>(); else cp_wait<0>();
        __syncthreads();
        if (it + 2 < 24) {
            load_stage((it + 2) % 3, (it + 2) * 32);
            cp_commit();
        }
        compute(it % 3);
    }

    // epilogue: bias + scatter; fp16 copies in natural layout
#pragma unroll
    for (int nt = 0; nt < 4; nt++) {
        const int ncol = n0 + wn * 32 + nt * 8 + 2 * lq;
        const float b0 = bi[ncol];
        const float b1 = bi[ncol + 1];
        const int h = ncol >> 6;
        const int d = ncol & 63;
#pragma unroll
        for (int mt = 0; mt < 2; mt++) {
            const int r = wm * 32 + mt * 16 + lr;
#pragma unroll
            for (int half = 0; half < 2; half++) {
                const int m = m0 + r + 8 * half;
                const int b = m >> 6;
                const int s = m & 63;
                const size_t bh = (size_t)b * NH + h;
                float2 v;
                v.x = acc[mt][nt][2 * half + 0] + b0;
                v.y = acc[mt][nt][2 * half + 1] + b1;
                const size_t idx = (bh * 64 + s) * 64 + d;
                if (mat == 0) {
                    *(__half2*)&g_qh[idx] = __floats2half2_rn(v.x, v.y);
                } else if (mat == 1) {
                    *(float2*)&out_k[idx] = v;
                    *(__half2*)&g_kh[idx] = __floats2half2_rn(v.x, v.y);
                } else {
                    *(float2*)&out_v[idx] = v;
                    *(__half2*)&g_vh[idx] = __floats2half2_rn(v.x, v.y);
                }
            }
        }
    }
}

// =====================================================================
// Flash cache attention, fp16 mma + ldmatrix. V consumed from natural
// [j][d] layout via ldmatrix.trans. Chunks 6,7 (c1) converted inline
// from fp32 (single-use data). (round-14 proven kernel, unchanged)
// =====================================================================
#define KVH_LD 72
#define KVH_TILE (64 * KVH_LD)
#define KROWB 144

__global__ __launch_bounds__(128, 4) void attn_flash_f16(
    const float* __restrict__ mask,
    const float* __restrict__ c1k, const float* __restrict__ c1v,
    float* __restrict__ outctx)
{
    extern __shared__ __half smh[];
    __half* kbuf   = smh;                       // [2][64][72]
    __half* vbuf   = kbuf + 2 * KVH_TILE;       // [2][64][72]
    float*  mask_s = (float*)(vbuf + 2 * KVH_TILE);   // [576]
    const uint32_t kb_b = smem_u32(kbuf);
    const uint32_t vb_b = smem_u32(vbuf);

    const int bh   = blockIdx.x;
    const int b    = bh / NH;
    const int h    = bh - b * NH;
    const int tid  = threadIdx.x;
    const int lane = tid & 31;
    const int w    = tid >> 5;
    const int lq   = lane & 3;
    const int lr   = lane >> 2;

    const int lg = lane >> 3, lrs = lane & 7;
    const int b_radd = (lg >> 1) * 8 + lrs;     // K (non-trans B)
    const int b_kadd = (lg & 1) * 8;
    const int v_radd = (lg & 1) * 8 + lrs;      // V (.trans)
    const int v_cadd = (lg >> 1) * 8;

    const __half* c0kb = g_c0kh + ((size_t)(b & 7) * NH + h) * L0 * HD;
    const __half* c0vb = g_c0vh + ((size_t)(b & 7) * NH + h) * L0 * HD;
    const float*  c1kf = c1k + (size_t)bh * L1 * HD;
    const float*  c1vf = c1v + (size_t)bh * L1 * HD;
    const __half* ksb  = g_kh + (size_t)bh * NS * HD;
    const __half* vsb  = g_vh + (size_t)bh * NS * HD;

    auto ksrc_of = [&](int c) -> const __half* {
        return (c < 6) ? (c0kb + c * 64 * HD) : ksb;
    };
    auto vsrc_of = [&](int c) -> const __half* {
        return (c < 6) ? (c0vb + c * 64 * HD) : vsb;
    };

    auto load_tile = [&](__half* buf, const __half* src) {
        const int r  = tid >> 1;
        const int c0 = (tid & 1) * 32;
        __half* d = buf + r * KVH_LD + c0;
        const __half* s = src + (size_t)r * HD + c0;
#pragma unroll
        for (int i = 0; i < 4; i++) cp16h(d + 8 * i, s + 8 * i);
    };

    auto cvt_tile = [&](__half* buf, const float* src) {
        const int r  = tid >> 1;
        const int cb = (tid & 1) * 32;
        const float* s = src + (size_t)r * HD + cb;
        __half* d = buf + r * KVH_LD + cb;
#pragma unroll
        for (int i = 0; i < 4; i++) {
            float4 v0 = *(const float4*)(s + 8 * i);
            float4 v1 = *(const float4*)(s + 8 * i + 4);
            uint4 o;
            o.x = h2u(__floats2half2_rn(v0.x, v0.y));
            o.y = h2u(__floats2half2_rn(v0.z, v0.w));
            o.z = h2u(__floats2half2_rn(v1.x, v1.y));
            o.w = h2u(__floats2half2_rn(v1.z, v1.w));
            *(uint4*)(d + 8 * i) = o;
        }
    };

    // prologue: Q -> kbuf[1]; chunk0 -> buf0; mask
    load_tile(kbuf + KVH_TILE, g_qh + (size_t)bh * NS * HD);
    cp_commit();
    load_tile(kbuf, ksrc_of(0));
    load_tile(vbuf, vsrc_of(0));
    cp_commit();
    for (int i = tid * 4; i < LTOT; i += 128 * 4)
        cp16f(mask_s + i, mask + (size_t)b * LTOT + i);
    cp_commit();

    cp_wait<2>();
    __syncthreads();

    uint32_t qa[4][4];
    {
        const int a_radd = (lg & 1) * 8 + lrs;
        const int a_kadd = (lg >> 1) * 8;
        const uint32_t Qb = kb_b + KVH_TILE * 2;
#pragma unroll
        for (int ks = 0; ks < 4; ks++) {
            const uint32_t addr = Qb
                + (uint32_t)((w * 16 + a_radd) * KROWB + (ks * 16 + a_kadd) * 2);
            ldm_x4(qa[ks][0], qa[ks][1], qa[ks][2], qa[ks][3], addr);
        }
    }
    __syncthreads();

    float m0 = -1e30f, m1 = -1e30f;
    float l0 = 0.f,    l1 = 0.f;
    float o[8][4];
#pragma unroll
    for (int dt = 0; dt < 8; dt++)
#pragma unroll
        for (int i = 0; i < 4; i++) o[dt][i] = 0.f;

    for (int c = 0; c < NCHUNK; c++) {
        const int nx = c + 1;
        if (nx < NCHUNK && nx != 6 && nx != 7) {
            load_tile(kbuf + (nx & 1) * KVH_TILE, ksrc_of(nx));
            load_tile(vbuf + (nx & 1) * KVH_TILE, vsrc_of(nx));
        }
        cp_commit();
        if (c < NCHUNK - 1) cp_wait<1>(); else cp_wait<0>();
        __syncthreads();

        if (c == 6 || c == 7) {
            cvt_tile(kbuf + (c & 1) * KVH_TILE, c1kf + (c - 6) * 64 * HD);
            cvt_tile(vbuf + (c & 1) * KVH_TILE, c1vf + (c - 6) * 64 * HD);
            __syncthreads();
        }

        const uint32_t Kb = kb_b + (c & 1) * KVH_TILE * 2;
        const uint32_t Vb = vb_b + (c & 1) * KVH_TILE * 2;

        // ---- S = Q K^T ----
        float cS[8][4];
#pragma unroll
        for (int nt = 0; nt < 8; nt++)
#pragma unroll
            for (int i = 0; i < 4; i++) cS[nt][i] = 0.f;

#pragma unroll
        for (int ks = 0; ks < 4; ks++) {
#pragma unroll
            for (int np = 0; np < 4; np++) {
                uint32_t b00, b01, b10, b11;
                const uint32_t addr = Kb
                    + (uint32_t)((np * 16 + b_radd) * KROWB + (ks * 16 + b_kadd) * 2);
                ldm_x4(b00, b01, b10, b11, addr);
                MMA_F16(cS[2 * np],     qa[ks], b00, b01);
                MMA_F16(cS[2 * np + 1], qa[ks], b10, b11);
            }
        }

        // ---- mask + scale + chunk row max ----
        float cm0 = -1e30f, cm1 = -1e30f;
#pragma unroll
        for (int nt = 0; nt < 8; nt++) {
            const int col = c * 64 + nt * 8 + 2 * lq;
            const float mv0 = mask_s[col];
            const float mv1 = mask_s[col + 1];
            cS[nt][0] = cS[nt][0] * 0.125f + mv0;
            cS[nt][1] = cS[nt][1] * 0.125f + mv1;
            cS[nt][2] = cS[nt][2] * 0.125f + mv0;
            cS[nt][3] = cS[nt][3] * 0.125f + mv1;
            cm0 = fmaxf(cm0, fmaxf(cS[nt][0], cS[nt][1]));
            cm1 = fmaxf(cm1, fmaxf(cS[nt][2], cS[nt][3]));
        }
#pragma unroll
        for (int off = 1; off <= 2; off <<= 1) {
            cm0 = fmaxf(cm0, __shfl_xor_sync(0xFFFFFFFFu, cm0, off));
            cm1 = fmaxf(cm1, __shfl_xor_sync(0xFFFFFFFFu, cm1, off));
        }

        const float mn0 = fmaxf(m0, cm0);
        const float mn1 = fmaxf(m1, cm1);
        const float a0  = __expf(m0 - mn0);
        const float a1  = __expf(m1 - mn1);
        m0 = mn0; m1 = mn1;

        float s0 = 0.f, s1 = 0.f;
#pragma unroll
        for (int nt = 0; nt < 8; nt++) {
            cS[nt][0] = __expf(cS[nt][0] - mn0);
            cS[nt][1] = __expf(cS[nt][1] - mn0);
            cS[nt][2] = __expf(cS[nt][2] - mn1);
            cS[nt][3] = __expf(cS[nt][3] - mn1);
            s0 += cS[nt][0] + cS[nt][1];
            s1 += cS[nt][2] + cS[nt][3];
        }
#pragma unroll
        for (int off = 1; off <= 2; off <<= 1) {
            s0 += __shfl_xor_sync(0xFFFFFFFFu, s0, off);
            s1 += __shfl_xor_sync(0xFFFFFFFFu, s1, off);
        }
        l0 = l0 * a0 + s0;
        l1 = l1 * a1 + s1;

#pragma unroll
        for (int dt = 0; dt < 8; dt++) {
            o[dt][0] *= a0; o[dt][1] *= a0;
            o[dt][2] *= a1; o[dt][3] *= a1;
        }

        // ---- PV: in-thread P pack, V via ldmatrix.trans ----
#pragma unroll
        for (int kt = 0; kt < 4; kt++) {
            uint32_t pa[4];
            pa[0] = h2u(__floats2half2_rn(cS[2 * kt][0],     cS[2 * kt][1]));
            pa[1] = h2u(__floats2half2_rn(cS[2 * kt][2],     cS[2 * kt][3]));
            pa[2] = h2u(__floats2half2_rn(cS[2 * kt + 1][0], cS[2 * kt + 1][1]));
            pa[3] = h2u(__floats2half2_rn(cS[2 * kt + 1][2], cS[2 * kt + 1][3]));
#pragma unroll
            for (int np = 0; np < 4; np++) {
                uint32_t b00, b01, b10, b11;
                const uint32_t addr = Vb
                    + (uint32_t)((kt * 16 + v_radd) * KROWB
                                 + (np * 16 + v_cadd) * 2);
                ldm_x4_t(b00, b01, b10, b11, addr);
                MMA_F16(o[2 * np],     pa, b00, b01);
                MMA_F16(o[2 * np + 1], pa, b10, b11);
            }
        }
        __syncthreads();
    }

    // epilogue: normalize + write out[b, s, h*64 + d]
    {
        const float r0 = 1.f / l0;
        const float r1 = 1.f / l1;
        const int r = w * 16 + lr;
        float* ob0 = outctx + ((size_t)b * NS + r) * NHID + h * HD;
        float* ob1 = outctx + ((size_t)b * NS + r + 8) * NHID + h * HD;
#pragma unroll
        for (int dt = 0; dt < 8; dt++) {
            const int dcol = dt * 8 + 2 * lq;
            float2 v0, v1;
            v0.x = o[dt][0] * r0; v0.y = o[dt][1] * r0;
            v1.x = o[dt][2] * r1; v1.y = o[dt][3] * r1;
            *(float2*)&ob0[dcol] = v0;
            *(float2*)&ob1[dcol] = v1;
        }
    }
}

// =====================================================================
// Host launcher
// =====================================================================
extern "C" void kernel_launch(void* const* d_in, const int* in_sizes, int n_in,
                              void* d_out, int out_size)
{
    const float* hidden = (const float*)d_in[0];
    const float* mask   = (const float*)d_in[1];
    const float* Wq     = (const float*)d_in[2];
    const float* bq     = (const float*)d_in[3];
    const float* Wk     = (const float*)d_in[4];
    const float* bk     = (const float*)d_in[5];
    const float* Wv     = (const float*)d_in[6];
    const float* bv     = (const float*)d_in[7];
    const float* c0k    = (const float*)d_in[8];
    const float* c0v    = (const float*)d_in[9];
    const float* c1k    = (const float*)d_in[10];
    const float* c1v    = (const float*)d_in[11];

    float* out   = (float*)d_out;
    const size_t sect = (size_t)NB * NS * NHID;
    float* out_k = out + sect;
    float* out_v = out + 2 * sect;

    __half *hidh_d, *wh_d, *c0kh_d, *c0vh_d;
    cudaGetSymbolAddress((void**)&hidh_d, g_hidh);
    cudaGetSymbolAddress((void**)&wh_d,   g_wh);
    cudaGetSymbolAddress((void**)&c0kh_d, g_c0kh);
    cudaGetSymbolAddress((void**)&c0vh_d, g_c0vh);

    const int gemm_smem = 3 * STAGEW * 4;                 // 61440
    const int attn_smem = 4 * KVH_TILE * 2 + LTOT * 4;    // 39168

    cudaFuncSetAttribute(qkv_gemm_f16,
                         cudaFuncAttributeMaxDynamicSharedMemorySize, gemm_smem);
    cudaFuncSetAttribute(attn_flash_f16,
                         cudaFuncAttributeMaxDynamicSharedMemorySize, attn_smem);

    // preprocessing: one fused convert launch (hidden, W, c0 only)
    cvt_all_kernel<<<4096, 256>>>(
        (const float4*)hidden, (const float4*)Wq, (const float4*)Wk,
        (const float4*)Wv, (const float4*)c0k, (const float4*)c0v,
        (uint2*)hidh_d, (uint2*)wh_d, (uint2*)c0kh_d, (uint2*)c0vh_d);

    dim3 ggrid(NB * NS / 128, 3 * NHID / 128);       // (120, 18)
    qkv_gemm_f16<<<ggrid, 512, gemm_smem>>>(bq, bk, bv, out_k, out_v);

    attn_flash_f16<<<NB * NH, 128, attn_smem>>>(mask, c1k, c1v, out);
}